// round 14
// baseline (speedup 1.0000x reference)
#include <cuda_runtime.h>
#include <math.h>

#define B 8
#define N 1024
#define C 256
#define K 256
#define C2 512
#define SCALE 0.17677669529663687f   // (C/H)^-0.5 = 1/sqrt(32)

// Output layout: [new_X (8*256*256) | new_adj (8*256*256) | new_mask (8*256)]
#define OUT_ADJ_OFF  (B*K*C)
#define OUT_MASK_OFF (2*B*K*C)

#define NCHUNK 64      // partial-sum chunks per batch (16 rows each)

// ---- scratch ----
__device__ float d_part[B*NCHUNK*C];
__device__ float d_u[B*C];
__device__ float d_scores[B*N];
__device__ int   d_idxg[B*K];
__device__ float d_gate[B*K];
__device__ float d_nm[B*K];

// ---------------------------------------------------------------------------
// K1: partial column sums of X (verbatim R2 — proven rounding).
// ---------------------------------------------------------------------------
__global__ void k_partial(const float* __restrict__ X) {
    int b = blockIdx.y, ch = blockIdx.x, c = threadIdx.x;
    const float* xp = X + ((size_t)b * N + (size_t)ch * 16) * C + c;
    float s = 0.f;
    #pragma unroll
    for (int r = 0; r < 16; r++) s += xp[(size_t)r * C];
    d_part[(b * NCHUNK + ch) * C + c] = s;
}

// ---------------------------------------------------------------------------
// K2: Xsum finish + two matvecs (verbatim R2 — proven rounding).
// ---------------------------------------------------------------------------
__global__ void k_uvec(const float* __restrict__ Wqkv) {
    int b = blockIdx.x, t = threadIdx.x;
    __shared__ float xs[C];
    __shared__ float ks[C];
    float s = 0.f;
    #pragma unroll
    for (int ch = 0; ch < NCHUNK; ch++) s += d_part[(b * NCHUNK + ch) * C + t];
    xs[t] = s;
    __syncthreads();
    float ka = 0.f;
    for (int c = 0; c < C; c++) ka += xs[c] * Wqkv[(size_t)c * C2 + C + t];
    ks[t] = ka;
    __syncthreads();
    const float* wrow = Wqkv + (size_t)t * C2;
    float ua = 0.f;
    for (int j = 0; j < C; j++) ua += wrow[j] * ks[j];
    d_u[b * C + t] = ua;
}

// ---------------------------------------------------------------------------
// K3: scores (verbatim R2 — proven rounding).
// ---------------------------------------------------------------------------
__global__ void k_scores(const float* __restrict__ X,
                         const float* __restrict__ mask) {
    int b = blockIdx.y, t = threadIdx.x;
    __shared__ float us[C];
    us[t] = d_u[b * C + t];
    __syncthreads();
    int warp = t >> 5, lane = t & 31;
    int n = blockIdx.x * 8 + warp;
    const float4* xr = (const float4*)(X + ((size_t)b * N + n) * C);
    const float4* ur = (const float4*)us;
    float acc = 0.f;
    #pragma unroll
    for (int it = 0; it < 2; it++) {
        float4 xv = xr[lane + it * 32];
        float4 uv = ur[lane + it * 32];
        acc += xv.x * uv.x + xv.y * uv.y + xv.z * uv.z + xv.w * uv.w;
    }
    #pragma unroll
    for (int o = 16; o; o >>= 1) acc += __shfl_xor_sync(0xffffffffu, acc, o);
    if (lane == 0) {
        float m = mask[b * N + n];
        d_scores[b * N + n] = (m > 0.f) ? SCALE * acc : -1e9f;
    }
}

// ---------------------------------------------------------------------------
// K4: top-k via exact histogram pruning + candidate ranking. grid (8), 1024.
// Key w = (orderedFloat(score)<<10) | (1023-i): distinct; larger w == higher
// score or equal score bits with smaller index (proven R10/R11 ordering).
// 1. 4096-bin histogram of top-12 key bits (order-independent int atomics).
// 2. Inclusive bin prefix scan -> nHigher(e) = 1024 - P[bin(e)] in O(1).
// 3. Candidate iff nHigher < K (superset of the true top-K).
// 4. Compact candidates; exact rank against candidate list only.
// All integer-exact => selection bit-identical to jax.lax.top_k.
// ---------------------------------------------------------------------------
__global__ void __launch_bounds__(1024, 1)
k_topk(const float* __restrict__ mask, float* __restrict__ out) {
    int b = blockIdx.x, t = threadIdx.x;
    int warp = t >> 5, lane = t & 31;
    __shared__ unsigned hist[4096];
    __shared__ unsigned long long cand[N];
    __shared__ unsigned wsum[32];
    __shared__ unsigned wpos[32];
    __shared__ float red[32];
    __shared__ int s_ki, s_ncand;

    // key + mask sum
    float f = d_scores[b * N + t];
    unsigned u = __float_as_uint(f);
    u = (u & 0x80000000u) ? ~u : (u | 0x80000000u);       // order-preserving
    unsigned long long key = ((unsigned long long)u << 10) | (unsigned)(N - 1 - t);

    float ms = mask[b * N + t];
    #pragma unroll
    for (int o = 16; o; o >>= 1) ms += __shfl_xor_sync(0xffffffffu, ms, o);
    if (lane == 0) red[warp] = ms;

    // zero histogram (4 bins/thread)
    hist[t] = 0; hist[t + 1024] = 0; hist[t + 2048] = 0; hist[t + 3072] = 0;
    __syncthreads();
    if (t == 0) {
        float s = 0.f;
        #pragma unroll
        for (int w2 = 0; w2 < 32; w2++) s += red[w2];
        s_ki = (int)ceilf(0.25f * s);
    }

    unsigned bin = (unsigned)(key >> 30);                  // top 12 bits
    atomicAdd(&hist[bin], 1u);
    __syncthreads();

    // inclusive prefix scan over 4096 bins (4 per thread)
    unsigned h0 = hist[4 * t], h1 = hist[4 * t + 1],
             h2 = hist[4 * t + 2], h3 = hist[4 * t + 3];
    unsigned a0 = h0, a1 = a0 + h1, a2 = a1 + h2, a3 = a2 + h3;
    unsigned s = a3;
    #pragma unroll
    for (int o = 1; o < 32; o <<= 1) {
        unsigned x = __shfl_up_sync(0xffffffffu, s, o);
        if (lane >= o) s += x;
    }
    if (lane == 31) wsum[warp] = s;
    __syncthreads();
    if (warp == 0) {
        unsigned v = wsum[lane];
        #pragma unroll
        for (int o = 1; o < 32; o <<= 1) {
            unsigned x = __shfl_up_sync(0xffffffffu, v, o);
            if (lane >= o) v += x;
        }
        wsum[lane] = v;
    }
    __syncthreads();
    unsigned base = (warp > 0 ? wsum[warp - 1] : 0u) + s - a3;
    hist[4 * t]     = base + a0;
    hist[4 * t + 1] = base + a1;
    hist[4 * t + 2] = base + a2;
    hist[4 * t + 3] = base + a3;
    __syncthreads();

    // candidate test: elements in strictly higher bins = N - P[bin]
    bool cf = (N - hist[bin]) < K;

    // compact candidates (ballot + two-level scan)
    unsigned bal = __ballot_sync(0xffffffffu, cf);
    int posw = __popc(bal & ((1u << lane) - 1u));
    if (lane == 0) wpos[warp] = (unsigned)__popc(bal);
    __syncthreads();
    if (warp == 0) {
        unsigned v = wpos[lane];
        #pragma unroll
        for (int o = 1; o < 32; o <<= 1) {
            unsigned x = __shfl_up_sync(0xffffffffu, v, o);
            if (lane >= o) v += x;
        }
        wpos[lane] = v;
        if (lane == 31) s_ncand = (int)v;
    }
    __syncthreads();
    if (cf) {
        int p = (int)(warp > 0 ? wpos[warp - 1] : 0u) + posw;
        cand[p] = key;
    }
    __syncthreads();

    // exact rank among candidates (uniform broadcast loop)
    if (cf) {
        int nc = s_ncand;
        int r0 = 0, r1 = 0;
        int i = 0;
        for (; i + 2 <= nc; i += 2) {
            r0 += (cand[i]     > key);
            r1 += (cand[i + 1] > key);
        }
        if (i < nc) r0 += (cand[i] > key);
        int rank = r0 + r1;
        if (rank < K) {
            int n = N - 1 - (int)(key & 0x3FFu);
            unsigned uh = (unsigned)(key >> 10);           // recover score bits
            unsigned orig = (uh & 0x80000000u) ? (uh & 0x7fffffffu) : ~uh;
            float val = __uint_as_float(orig);
            float nm = (rank < s_ki) ? 1.f : 0.f;
            d_idxg[b * K + rank] = n;
            d_gate[b * K + rank] = tanhf(val) * nm;
            d_nm[b * K + rank]   = nm;
            out[OUT_MASK_OFF + b * K + rank] = nm;
        }
    }
}

// ---------------------------------------------------------------------------
// K5: gather, 4 rows per block, 512 threads (verbatim R12). grid (64, 8).
//   new_X[b,i,:]   = X[b, idx[i], :] * gate[i]
//   new_adj[b,i,j] = adj[b, idx[i], idx[j]] * nm[i]*nm[j]
// ---------------------------------------------------------------------------
__global__ void k_gather(const float* __restrict__ X,
                         const float* __restrict__ adj,
                         float* __restrict__ out) {
    int b = blockIdx.y, i0 = blockIdx.x * 4, t = threadIdx.x;
    __shared__ int   sidx[K];
    __shared__ float snm[K];
    __shared__ float sg[4];
    __shared__ __align__(16) float srow[4][N];

    if (t < 256) {
        sidx[t] = d_idxg[b * K + t];
        snm[t]  = d_nm[b * K + t];
    }
    if (t >= 256 && t < 260) sg[t - 256] = d_gate[b * K + i0 + (t - 256)];
    __syncthreads();

    const float* adjb = adj + (size_t)b * N * N;
    #pragma unroll
    for (int rr = 0; rr < 2; rr++) {
        int lin = rr * 512 + t;
        int row = lin >> 8;
        int q   = lin & 255;
        const float4* src = (const float4*)(adjb + (size_t)sidx[i0 + row] * N);
        ((float4*)srow[row])[q] = src[q];
    }
    #pragma unroll
    for (int rr = 0; rr < 2; rr++) {
        int lin = rr * 512 + t;
        int row = lin >> 8;
        int col = lin & 255;
        int ri  = sidx[i0 + row];
        out[((size_t)b * K + i0 + row) * C + col] =
            X[((size_t)b * N + ri) * C + col] * sg[row];
    }
    __syncthreads();

    #pragma unroll
    for (int rr = 0; rr < 2; rr++) {
        int lin = rr * 512 + t;
        int row = lin >> 8;
        int j   = lin & 255;
        float vv = srow[row][sidx[j]] * snm[i0 + row] * snm[j];
        out[OUT_ADJ_OFF + ((size_t)b * K + i0 + row) * K + j] = vv;
    }
}

// ---------------------------------------------------------------------------
extern "C" void kernel_launch(void* const* d_in, const int* in_sizes, int n_in,
                              void* d_out, int out_size) {
    const float* X    = (const float*)d_in[0];
    const float* adj  = (const float*)d_in[1];
    const float* mask = (const float*)d_in[2];
    const float* Wqkv = (const float*)d_in[3];
    float* out = (float*)d_out;

    k_partial<<<dim3(NCHUNK, B), 256>>>(X);
    k_uvec<<<B, 256>>>(Wqkv);
    k_scores<<<dim3(N / 8, B), 256>>>(X, mask);
    k_topk<<<B, 1024>>>(mask, out);
    k_gather<<<dim3(K / 4, B), 512>>>(X, adj, out);
}

// round 15
// speedup vs baseline: 1.2561x; 1.2561x over previous
#include <cuda_runtime.h>
#include <math.h>

#define B 8
#define N 1024
#define C 256
#define K 256
#define C2 512
#define SCALE 0.17677669529663687f   // (C/H)^-0.5 = 1/sqrt(32)

// Output layout: [new_X (8*256*256) | new_adj (8*256*256) | new_mask (8*256)]
#define OUT_ADJ_OFF  (B*K*C)
#define OUT_MASK_OFF (2*B*K*C)

#define NCHUNK 64      // partial-sum chunks per batch (16 rows each)

// ---- scratch ----
__device__ float d_part[B*NCHUNK*C];
__device__ float d_u[B*C];
__device__ float d_scores[B*N];
__device__ int   d_idxg[B*K];
__device__ float d_gate[B*K];
__device__ float d_nm[B*K];

// ---------------------------------------------------------------------------
// K1: partial column sums of X (verbatim R2 — proven rounding).
// ---------------------------------------------------------------------------
__global__ void k_partial(const float* __restrict__ X) {
    int b = blockIdx.y, ch = blockIdx.x, c = threadIdx.x;
    const float* xp = X + ((size_t)b * N + (size_t)ch * 16) * C + c;
    float s = 0.f;
    #pragma unroll
    for (int r = 0; r < 16; r++) s += xp[(size_t)r * C];
    d_part[(b * NCHUNK + ch) * C + c] = s;
}

// ---------------------------------------------------------------------------
// K2: Xsum finish + two matvecs (verbatim R2 — proven rounding).
// ---------------------------------------------------------------------------
__global__ void k_uvec(const float* __restrict__ Wqkv) {
    int b = blockIdx.x, t = threadIdx.x;
    __shared__ float xs[C];
    __shared__ float ks[C];
    float s = 0.f;
    #pragma unroll
    for (int ch = 0; ch < NCHUNK; ch++) s += d_part[(b * NCHUNK + ch) * C + t];
    xs[t] = s;
    __syncthreads();
    float ka = 0.f;
    for (int c = 0; c < C; c++) ka += xs[c] * Wqkv[(size_t)c * C2 + C + t];
    ks[t] = ka;
    __syncthreads();
    const float* wrow = Wqkv + (size_t)t * C2;
    float ua = 0.f;
    for (int j = 0; j < C; j++) ua += wrow[j] * ks[j];
    d_u[b * C + t] = ua;
}

// ---------------------------------------------------------------------------
// K3: scores (verbatim R2 — proven rounding).
// ---------------------------------------------------------------------------
__global__ void k_scores(const float* __restrict__ X,
                         const float* __restrict__ mask) {
    int b = blockIdx.y, t = threadIdx.x;
    __shared__ float us[C];
    us[t] = d_u[b * C + t];
    __syncthreads();
    int warp = t >> 5, lane = t & 31;
    int n = blockIdx.x * 8 + warp;
    const float4* xr = (const float4*)(X + ((size_t)b * N + n) * C);
    const float4* ur = (const float4*)us;
    float acc = 0.f;
    #pragma unroll
    for (int it = 0; it < 2; it++) {
        float4 xv = xr[lane + it * 32];
        float4 uv = ur[lane + it * 32];
        acc += xv.x * uv.x + xv.y * uv.y + xv.z * uv.z + xv.w * uv.w;
    }
    #pragma unroll
    for (int o = 16; o; o >>= 1) acc += __shfl_xor_sync(0xffffffffu, acc, o);
    if (lane == 0) {
        float m = mask[b * N + n];
        d_scores[b * N + n] = (m > 0.f) ? SCALE * acc : -1e9f;
    }
}

// ---------------------------------------------------------------------------
// K4: top-k (verbatim R13 — best measured top-k, 9.0us, proven).
// Virtual-processor bitonic: 256 threads x 4 elements, e = t + 256*m.
// ---------------------------------------------------------------------------
__global__ void __launch_bounds__(256, 1)
k_topk(const float* __restrict__ mask, float* __restrict__ out) {
    int b = blockIdx.x, t = threadIdx.x;
    __shared__ unsigned long long sx[4][256];
    __shared__ float red[8];
    __shared__ int s_ki;

    unsigned long long v[4];
    float msum = 0.f;
    #pragma unroll
    for (int m = 0; m < 4; m++) {
        int e = t + 256 * m;
        float f = d_scores[b * N + e];
        unsigned u = __float_as_uint(f);
        u = (u & 0x80000000u) ? ~u : (u | 0x80000000u);
        v[m] = ((unsigned long long)(~u) << 32) | (unsigned)e;
        msum += mask[b * N + e];
    }
    #pragma unroll
    for (int o = 16; o; o >>= 1) msum += __shfl_xor_sync(0xffffffffu, msum, o);
    if ((t & 31) == 0) red[t >> 5] = msum;
    __syncthreads();
    if (t == 0) {
        float s = 0.f;
        #pragma unroll
        for (int w = 0; w < 8; w++) s += red[w];
        s_ki = (int)ceilf(0.25f * s);
    }
    __syncthreads();

    #pragma unroll
    for (unsigned k = 2; k <= 1024; k <<= 1) {
        #pragma unroll
        for (unsigned j = 512; j > 0; j >>= 1) {
            if (j > (k >> 1)) continue;
            if (j >= 256) {
                int jm = (int)(j >> 8);
                #pragma unroll
                for (int m = 0; m < 4; m++) {
                    if ((m & jm) == 0) {
                        int mp = m | jm;
                        bool up = (k == 1024) ? true : ((m & 2) == 0);
                        unsigned long long a = v[m], bb = v[mp];
                        unsigned long long mn = a < bb ? a : bb;
                        unsigned long long mx = a < bb ? bb : a;
                        v[m]  = up ? mn : mx;
                        v[mp] = up ? mx : mn;
                    }
                }
            } else if (j >= 32) {
                #pragma unroll
                for (int m = 0; m < 4; m++) sx[m][t] = v[m];
                __syncthreads();
                bool lower = ((t & j) == 0);
                #pragma unroll
                for (int m = 0; m < 4; m++) {
                    bool up;
                    if (k <= 128)       up = ((t & k) == 0);
                    else if (k == 256)  up = ((m & 1) == 0);
                    else if (k == 512)  up = ((m & 2) == 0);
                    else                up = true;
                    unsigned long long w = sx[m][t ^ j];
                    bool takeMin = (lower == up);
                    v[m] = takeMin ? (v[m] < w ? v[m] : w)
                                   : (v[m] > w ? v[m] : w);
                }
                __syncthreads();
            } else {
                bool lower = ((t & j) == 0);
                #pragma unroll
                for (int m = 0; m < 4; m++) {
                    bool up;
                    if (k <= 128)       up = ((t & k) == 0);
                    else if (k == 256)  up = ((m & 1) == 0);
                    else if (k == 512)  up = ((m & 2) == 0);
                    else                up = true;
                    unsigned long long w = __shfl_xor_sync(0xffffffffu, v[m], j);
                    bool takeMin = (lower == up);
                    v[m] = takeMin ? (v[m] < w ? v[m] : w)
                                   : (v[m] > w ? v[m] : w);
                }
            }
        }
    }

    {
        unsigned long long key = v[0];
        int n = (int)(unsigned)key;
        unsigned uh = ~(unsigned)(key >> 32);
        unsigned orig = (uh & 0x80000000u) ? (uh & 0x7fffffffu) : ~uh;
        float val = __uint_as_float(orig);
        float nm = (t < s_ki) ? 1.f : 0.f;
        d_idxg[b * K + t] = n;
        d_gate[b * K + t] = tanhf(val) * nm;
        d_nm[b * K + t]   = nm;
        out[OUT_MASK_OFF + b * K + t] = nm;
    }
}

// ---------------------------------------------------------------------------
// K5: gather, 1 row/block, single barrier. grid (256, 8), 256 threads.
// ri/nm_i/gate_i loaded directly from gmem (uniform broadcast) so the adj-row
// and X-row loads overlap the sidx/snm staging instead of waiting behind a
// barrier — cuts one ~600-cycle gmem round trip off the block critical path.
//   new_X[b,i,:]   = X[b, idx[i], :] * gate[i]          (coalesced)
//   new_adj[b,i,j] = adj[b, idx[i], idx[j]] * nm[i]*nm[j]
// ---------------------------------------------------------------------------
__global__ void k_gather(const float* __restrict__ X,
                         const float* __restrict__ adj,
                         float* __restrict__ out) {
    int b = blockIdx.y, i = blockIdx.x, t = threadIdx.x;
    __shared__ int   sidx[K];
    __shared__ float snm[K];
    __shared__ __align__(16) float srow[N];

    // uniform per-block scalars straight from gmem — no barrier dependency
    int   ri  = d_idxg[b * K + i];
    float nmi = d_nm[b * K + i];
    float gte = d_gate[b * K + i];

    // stage the index/mask vectors concurrently with the row loads below
    sidx[t] = d_idxg[b * K + t];
    snm[t]  = d_nm[b * K + t];

    // adj row (4KB) coalesced — depends only on ri
    {
        const float4* row4 = (const float4*)(adj + (size_t)b * N * N + (size_t)ri * N);
        ((float4*)srow)[t] = row4[t];
    }
    // new_X row (coalesced read+write), overlapped with adj staging
    out[((size_t)b * K + i) * C + t] = X[((size_t)b * N + ri) * C + t] * gte;
    __syncthreads();

    out[OUT_ADJ_OFF + ((size_t)b * K + i) * K + t] = srow[sidx[t]] * nmi * snm[t];
}

// ---------------------------------------------------------------------------
extern "C" void kernel_launch(void* const* d_in, const int* in_sizes, int n_in,
                              void* d_out, int out_size) {
    const float* X    = (const float*)d_in[0];
    const float* adj  = (const float*)d_in[1];
    const float* mask = (const float*)d_in[2];
    const float* Wqkv = (const float*)d_in[3];
    float* out = (float*)d_out;

    k_partial<<<dim3(NCHUNK, B), 256>>>(X);
    k_uvec<<<B, 256>>>(Wqkv);
    k_scores<<<dim3(N / 8, B), 256>>>(X, mask);
    k_topk<<<B, 256>>>(mask, out);
    k_gather<<<dim3(K, B), 256>>>(X, adj, out);
}